// round 9
// baseline (speedup 1.0000x reference)
#include <cuda_runtime.h>
#include <cuda_fp16.h>

#define NMAX 100000
#define EMAX 1600000
#define DD 128
#define NG 512

// ---------------- device scratch (static, no allocs) ----------------
__device__ int   g_is64;
__device__ int   g_cnt[NMAX];
__device__ float g_dis[NMAX];
__device__ int   g_tmp[NMAX];
__device__ int   g_bsum[256];
__device__ int   g_rowptr[NMAX + 1];
__device__ int   g_cursor[NMAX];
__device__ int2  g_edge[EMAX];
__device__ __align__(256) float g_bufA[(size_t)NMAX * DD];
__device__ __align__(256) float g_bufB[(size_t)NMAX * DD];
__device__ __align__(256) float g_agg[(size_t)NMAX * DD];
__device__ __align__(256) __half g_h16[(size_t)NMAX * DD];
__device__ __align__(256) __half g_W16[4 * DD * DD];   // swizzled W^T fp16 per layer
__device__ float g_gsum[NG];
__device__ float g_gcnt[NG];

__device__ __forceinline__ int ld_idx(const void* p, long long i) {
    if (g_is64) return (int)((const long long*)p)[i];
    return ((const int*)p)[i];
}

// ---------------- zero + dtype detect ----------------
__global__ void k_zero_detect(const void* ei) {
    int i = blockIdx.x * blockDim.x + threadIdx.x;
    if (i < NMAX) g_cnt[i] = 0;
    if (i < NG) { g_gsum[i] = 0.f; g_gcnt[i] = 0.f; }
    if (i == 0) {
        const unsigned long long* p = (const unsigned long long*)ei;
        int ok = 1;
        for (int j = 0; j < 16; j++)
            if (p[j] >> 32) ok = 0;
        g_is64 = ok;
    }
}

// ---------------- degree count + graph counts ----------------
__global__ void k_count(const void* ei, const void* batch, int e, int n) {
    int i = blockIdx.x * blockDim.x + threadIdx.x;
    if (i < e) {
        int d = ld_idx(ei, (long long)e + i);
        atomicAdd(&g_cnt[d], 1);
    }
    if (i < n) {
        int g = ld_idx(batch, i);
        atomicAdd(&g_gcnt[g], 1.f);
    }
}

// ---------------- x -> fp16 ----------------
__global__ void k_x2h(const float* __restrict__ x, int n) {
    int i = blockIdx.x * blockDim.x + threadIdx.x;   // one float4 per thread
    if (i >= n * 32) return;
    float4 v = ((const float4*)x)[i];
    __half2 p0 = __floats2half2_rn(v.x, v.y);
    __half2 p1 = __floats2half2_rn(v.z, v.w);
    uint2 u;
    u.x = *(unsigned int*)&p0;
    u.y = *(unsigned int*)&p1;
    ((uint2*)g_h16)[i] = u;
}

// ---------------- W -> fp16 transposed + swizzled ----------------
__global__ void k_wprep(const float* __restrict__ Ws) {
    int idx = blockIdx.x * blockDim.x + threadIdx.x;   // 65536
    int l = idx >> 14, rem = idx & 16383;
    int c = rem & 127, k = rem >> 7;
    float w = Ws[l * 16384 + k * 128 + c];
    int kg = k >> 3;
    g_W16[l * 16384 + c * 128 + ((((kg ^ (c & 7)) << 3)) | (k & 7))] = __float2half(w);
}

// ---------------- scan phase 1 ----------------
__global__ void k_scan1(int n) {
    __shared__ int s[512];
    int t = threadIdx.x;
    int i = blockIdx.x * 512 + t;
    int v = (i < n) ? g_cnt[i] : 0;
    s[t] = v;
    __syncthreads();
    for (int off = 1; off < 512; off <<= 1) {
        int x = 0;
        if (t >= off) x = s[t - off];
        __syncthreads();
        s[t] += x;
        __syncthreads();
    }
    if (i < n) g_tmp[i] = s[t];
    if (t == 511) g_bsum[blockIdx.x] = s[511];
}

// ---------------- scan phases 2+3 merged ----------------
__global__ void k_scan23(int nb, int n) {
    __shared__ int sb[256];
    int t = threadIdx.x;
    if (t < 256) sb[t] = (t < nb) ? g_bsum[t] : 0;
    __syncthreads();
    for (int off = 1; off < 256; off <<= 1) {
        int x = 0;
        if (t < 256 && t >= off) x = sb[t - off];
        __syncthreads();
        if (t < 256) sb[t] += x;
        __syncthreads();
    }
    int boff = (blockIdx.x > 0) ? sb[blockIdx.x - 1] : 0;
    if (blockIdx.x == 0 && t == 0) g_rowptr[n] = sb[255];
    int i = blockIdx.x * 512 + t;
    if (i < n) {
        int rp = g_tmp[i] - g_cnt[i] + boff;
        g_rowptr[i] = rp;
        g_cursor[i] = rp;
        g_dis[i] = rsqrtf((float)g_cnt[i] + 1.0f);
    }
}

// ---------------- CSR fill ----------------
__global__ void k_fill(const void* ei, int e) {
    int i = blockIdx.x * blockDim.x + threadIdx.x;
    if (i < e) {
        int s = ld_idx(ei, i);
        int d = ld_idx(ei, (long long)e + i);
        int pos = atomicAdd(&g_cursor[d], 1);
        g_edge[pos] = make_int2(s, __float_as_int(g_dis[s] * g_dis[d]));
    }
}

// ---------------- aggregation: warp per node, LDG.128 fp16 gather, 2 edges/step ----------------
// 16 lanes cover one 256B row; half-warp h processes edges 2j+h. Cross-half combine at end.
__global__ __launch_bounds__(256, 8) void k_agg(const float* __restrict__ selfbuf, int n) {
    int nwarps = gridDim.x << 3;
    int lane = threadIdx.x & 31;
    int h = lane >> 4, l16 = lane & 15;
    const uint4* in16 = (const uint4*)g_h16;   // one row = 16 uint4
    for (int w = (blockIdx.x << 3) + (threadIdx.x >> 5); w < n; w += nwarps) {
        float4 acc0 = make_float4(0.f, 0.f, 0.f, 0.f);
        float4 acc1 = make_float4(0.f, 0.f, 0.f, 0.f);
        if (h == 0) {
            float ds = g_dis[w];
            float self = ds * ds;
            float4 a0 = ((const float4*)selfbuf)[(size_t)w * 32 + l16 * 2];
            float4 a1 = ((const float4*)selfbuf)[(size_t)w * 32 + l16 * 2 + 1];
            acc0.x = a0.x * self; acc0.y = a0.y * self; acc0.z = a0.z * self; acc0.w = a0.w * self;
            acc1.x = a1.x * self; acc1.y = a1.y * self; acc1.z = a1.z * self; acc1.w = a1.w * self;
        }

        int beg = g_rowptr[w], end = g_rowptr[w + 1];
        for (int base = beg; base < end; base += 32) {
            int e = base + lane;
            int s = 0; float c = 0.f;
            if (e < end) { int2 ed = g_edge[e]; s = ed.x; c = __int_as_float(ed.y); }
            int m = min(32, end - base);
            int npairs = (m + 1) >> 1;
            int jj = 0;
            for (; jj + 8 <= npairs; jj += 8) {
                int si[8]; float ci[8]; uint4 ui[8];
#pragma unroll
                for (int j = 0; j < 8; j++) {
                    int idx = 2 * (jj + j) + h;    // lanes past m carry s=0,c=0 -> harmless
                    si[j] = __shfl_sync(0xffffffffu, s, idx);
                    ci[j] = __shfl_sync(0xffffffffu, c, idx);
                }
#pragma unroll
                for (int j = 0; j < 8; j++) ui[j] = in16[(size_t)si[j] * 16 + l16];
#pragma unroll
                for (int j = 0; j < 8; j++) {
                    float2 f0 = __half22float2(*(__half2*)&ui[j].x);
                    float2 f1 = __half22float2(*(__half2*)&ui[j].y);
                    float2 f2 = __half22float2(*(__half2*)&ui[j].z);
                    float2 f3 = __half22float2(*(__half2*)&ui[j].w);
                    acc0.x += ci[j] * f0.x; acc0.y += ci[j] * f0.y;
                    acc0.z += ci[j] * f1.x; acc0.w += ci[j] * f1.y;
                    acc1.x += ci[j] * f2.x; acc1.y += ci[j] * f2.y;
                    acc1.z += ci[j] * f3.x; acc1.w += ci[j] * f3.y;
                }
            }
            for (; jj < npairs; jj++) {
                int idx = 2 * jj + h;
                int ss = __shfl_sync(0xffffffffu, s, idx);
                float cc = __shfl_sync(0xffffffffu, c, idx);
                uint4 u = in16[(size_t)ss * 16 + l16];
                float2 f0 = __half22float2(*(__half2*)&u.x);
                float2 f1 = __half22float2(*(__half2*)&u.y);
                float2 f2 = __half22float2(*(__half2*)&u.z);
                float2 f3 = __half22float2(*(__half2*)&u.w);
                acc0.x += cc * f0.x; acc0.y += cc * f0.y;
                acc0.z += cc * f1.x; acc0.w += cc * f1.y;
                acc1.x += cc * f2.x; acc1.y += cc * f2.y;
                acc1.z += cc * f3.x; acc1.w += cc * f3.y;
            }
        }
        // combine the two half-warps (same k-positions at lane^16)
        acc0.x += __shfl_xor_sync(0xffffffffu, acc0.x, 16);
        acc0.y += __shfl_xor_sync(0xffffffffu, acc0.y, 16);
        acc0.z += __shfl_xor_sync(0xffffffffu, acc0.z, 16);
        acc0.w += __shfl_xor_sync(0xffffffffu, acc0.w, 16);
        acc1.x += __shfl_xor_sync(0xffffffffu, acc1.x, 16);
        acc1.y += __shfl_xor_sync(0xffffffffu, acc1.y, 16);
        acc1.z += __shfl_xor_sync(0xffffffffu, acc1.z, 16);
        acc1.w += __shfl_xor_sync(0xffffffffu, acc1.w, 16);
        if (h == 0) {
            ((float4*)g_agg)[(size_t)w * 32 + l16 * 2] = acc0;
            ((float4*)g_agg)[(size_t)w * 32 + l16 * 2 + 1] = acc1;
        }
    }
}

// ---------------- tensor-core transform: HMMA GEMM + bias + LN + res + relu + pool ----------------
#define TSMEM (16384 + 32768 + 3 * 512)

__global__ void k_transform_mma(
    const float* __restrict__ bs,
    const float* __restrict__ gammas, const float* __restrict__ betas,
    const float* __restrict__ lin_w, const void* __restrict__ batch,
    int layer, int ressel, int outsel, int dorelu, int dopool, int doh16, int n)
{
    extern __shared__ char smem[];
    __half* sA = (__half*)smem;                       // swizzled: r*128 + ((kg^(r&7))<<3 | k&7)
    __half* sW = (__half*)(smem + 16384);             // swizzled-T: c*128 + ((kg^(c&7))<<3 | k&7)
    float*  sS = (float*)(smem + 49152);              // [2][64]
    float*  sQ = sS + 128;
    float*  sP = sQ + 128;

    int t = threadIdx.x;
    int warp = t >> 5, lane = t & 31;
    int rt = warp >> 1, cgp = warp & 1;
    int g = lane >> 2, tq = lane & 3;

    {
        const uint4* src = (const uint4*)(g_W16 + (size_t)layer * DD * DD);
        uint4* dst = (uint4*)sW;
#pragma unroll
        for (int j = 0; j < 8; j++) dst[t + j * 256] = src[t + j * 256];
    }

    int mi = lane >> 3, li = lane & 7;
    int r_lm = rt * 16 + ((mi & 1) << 3) + li;
    int kgx = mi >> 1;
    unsigned sA_u32 = (unsigned)__cvta_generic_to_shared(sA);
    unsigned aRowBase = sA_u32 + r_lm * 256;

    const float2* res2 = (ressel == 1) ? (const float2*)g_bufA
                       : (ressel == 2) ? (const float2*)g_bufB : (const float2*)0;
    float2* out2 = (outsel == 1) ? (float2*)g_bufA
                 : (outsel == 2) ? (float2*)g_bufB : (float2*)0;

    int ntiles = (n + 63) >> 6;
    for (int tile = blockIdx.x; tile < ntiles; tile += gridDim.x) {
        int row0 = tile << 6;
        __syncthreads();

        {
            const float4* agg4 = (const float4*)g_agg;
#pragma unroll
            for (int j = 0; j < 4; j++) {
                int idx = t + j * 256;
                int r = idx >> 4, kg = idx & 15;
                int row = row0 + r;
                float4 v0, v1;
                if (row < n) {
                    v0 = agg4[(size_t)row * 32 + kg * 2];
                    v1 = agg4[(size_t)row * 32 + kg * 2 + 1];
                } else {
                    v0 = make_float4(0.f, 0.f, 0.f, 0.f);
                    v1 = v0;
                }
                __half2 h0 = __floats2half2_rn(v0.x, v0.y);
                __half2 h1 = __floats2half2_rn(v0.z, v0.w);
                __half2 h2 = __floats2half2_rn(v1.x, v1.y);
                __half2 h3 = __floats2half2_rn(v1.z, v1.w);
                uint4 u;
                u.x = *(unsigned*)&h0; u.y = *(unsigned*)&h1;
                u.z = *(unsigned*)&h2; u.w = *(unsigned*)&h3;
                *(uint4*)&sA[r * 128 + ((kg ^ (r & 7)) << 3)] = u;
            }
        }
        __syncthreads();

        float d[8][4];
#pragma unroll
        for (int i = 0; i < 8; i++) { d[i][0] = 0.f; d[i][1] = 0.f; d[i][2] = 0.f; d[i][3] = 0.f; }

#pragma unroll
        for (int ks = 0; ks < 8; ks++) {
            int kg = 2 * ks + kgx;
            unsigned addr = aRowBase + ((kg ^ (r_lm & 7)) << 4);
            unsigned a0, a1, a2, a3;
            asm volatile("ldmatrix.sync.aligned.m8n8.x4.shared.b16 {%0,%1,%2,%3}, [%4];"
                         : "=r"(a0), "=r"(a1), "=r"(a2), "=r"(a3) : "r"(addr));
            int k0 = ks * 16 + 2 * tq;
            int kga = (k0 >> 3), kgb = ((k0 + 8) >> 3);
#pragma unroll
            for (int nt = 0; nt < 8; nt++) {
                int c = cgp * 64 + nt * 8 + g;
                unsigned b0 = *(unsigned*)&sW[c * 128 + (((kga ^ (c & 7)) << 3) | (k0 & 7))];
                unsigned b1 = *(unsigned*)&sW[c * 128 + (((kgb ^ (c & 7)) << 3) | (k0 & 7))];
                asm("mma.sync.aligned.m16n8k16.row.col.f32.f16.f16.f32 "
                    "{%0,%1,%2,%3}, {%4,%5,%6,%7}, {%8,%9}, {%0,%1,%2,%3};"
                    : "+f"(d[nt][0]), "+f"(d[nt][1]), "+f"(d[nt][2]), "+f"(d[nt][3])
                    : "r"(a0), "r"(a1), "r"(a2), "r"(a3), "r"(b0), "r"(b1));
            }
        }

#pragma unroll
        for (int nt = 0; nt < 8; nt++) {
            int cb = cgp * 64 + nt * 8 + 2 * tq;
            float2 bv = *(const float2*)&bs[layer * DD + cb];
            d[nt][0] += bv.x; d[nt][1] += bv.y;
            d[nt][2] += bv.x; d[nt][3] += bv.y;
        }

        float sG = 0.f, qG = 0.f, sH = 0.f, qH = 0.f;
#pragma unroll
        for (int nt = 0; nt < 8; nt++) {
            sG += d[nt][0] + d[nt][1];
            qG += d[nt][0] * d[nt][0] + d[nt][1] * d[nt][1];
            sH += d[nt][2] + d[nt][3];
            qH += d[nt][2] * d[nt][2] + d[nt][3] * d[nt][3];
        }
#pragma unroll
        for (int off = 1; off <= 2; off <<= 1) {
            sG += __shfl_xor_sync(0xffffffffu, sG, off);
            qG += __shfl_xor_sync(0xffffffffu, qG, off);
            sH += __shfl_xor_sync(0xffffffffu, sH, off);
            qH += __shfl_xor_sync(0xffffffffu, qH, off);
        }
        int rA_l = rt * 16 + g, rB_l = rA_l + 8;
        if (tq == 0) {
            sS[cgp * 64 + rA_l] = sG; sQ[cgp * 64 + rA_l] = qG;
            sS[cgp * 64 + rB_l] = sH; sQ[cgp * 64 + rB_l] = qH;
        }
        __syncthreads();
        float sa = sS[rA_l] + sS[64 + rA_l];
        float qa = sQ[rA_l] + sQ[64 + rA_l];
        float sb2 = sS[rB_l] + sS[64 + rB_l];
        float qb2 = sQ[rB_l] + sQ[64 + rB_l];
        float muA = sa * (1.0f / 128.0f);
        float isdA = rsqrtf(qa * (1.0f / 128.0f) - muA * muA + 1e-5f);
        float muB = sb2 * (1.0f / 128.0f);
        float isdB = rsqrtf(qb2 * (1.0f / 128.0f) - muB * muB + 1e-5f);

        int rowA = row0 + rA_l;
        int rowB = row0 + rB_l;
        bool okA = rowA < n, okB = rowB < n;
        float pA = 0.f, pB = 0.f;

#pragma unroll
        for (int nt = 0; nt < 8; nt++) {
            int cb = cgp * 64 + nt * 8 + 2 * tq;
            float2 gv = *(const float2*)&gammas[layer * DD + cb];
            float2 be = *(const float2*)&betas[layer * DD + cb];
            float o0 = (d[nt][0] - muA) * isdA * gv.x + be.x;
            float o1 = (d[nt][1] - muA) * isdA * gv.y + be.y;
            float o2 = (d[nt][2] - muB) * isdB * gv.x + be.x;
            float o3 = (d[nt][3] - muB) * isdB * gv.y + be.y;
            if (res2) {
                if (okA) { float2 r = res2[(size_t)rowA * 64 + (cb >> 1)]; o0 += r.x; o1 += r.y; }
                if (okB) { float2 r = res2[(size_t)rowB * 64 + (cb >> 1)]; o2 += r.x; o3 += r.y; }
            }
            if (dorelu) {
                o0 = fmaxf(o0, 0.f); o1 = fmaxf(o1, 0.f);
                o2 = fmaxf(o2, 0.f); o3 = fmaxf(o3, 0.f);
            }
            if (out2) {
                if (okA) out2[(size_t)rowA * 64 + (cb >> 1)] = make_float2(o0, o1);
                if (okB) out2[(size_t)rowB * 64 + (cb >> 1)] = make_float2(o2, o3);
            }
            if (doh16) {
                if (okA) *(__half2*)&g_h16[(size_t)rowA * DD + cb] = __floats2half2_rn(o0, o1);
                if (okB) *(__half2*)&g_h16[(size_t)rowB * DD + cb] = __floats2half2_rn(o2, o3);
            }
            if (dopool) {
                float2 lw = *(const float2*)&lin_w[cb];
                pA += o0 * lw.x + o1 * lw.y;
                pB += o2 * lw.x + o3 * lw.y;
            }
        }

        if (dopool) {
#pragma unroll
            for (int off = 1; off <= 2; off <<= 1) {
                pA += __shfl_xor_sync(0xffffffffu, pA, off);
                pB += __shfl_xor_sync(0xffffffffu, pB, off);
            }
            if (tq == 0) {
                sP[cgp * 64 + rA_l] = pA;
                sP[cgp * 64 + rB_l] = pB;
            }
            __syncthreads();
            if (t < 64) {
                int row = row0 + t;
                if (row < n) {
                    float p = sP[t] + sP[64 + t];
                    int gr = ld_idx(batch, row);
                    atomicAdd(&g_gsum[gr], p);
                }
            }
        }
    }
}

// ---------------- final ----------------
__global__ void k_final(const float* __restrict__ lin_b, float* __restrict__ out) {
    int g = blockIdx.x * blockDim.x + threadIdx.x;
    if (g < NG) out[g] = g_gsum[g] / fmaxf(g_gcnt[g], 1.f) + lin_b[0];
}

// ---------------- launch ----------------
extern "C" void kernel_launch(void* const* d_in, const int* in_sizes, int n_in,
                              void* d_out, int out_size) {
    const float* x      = (const float*)d_in[0];
    const void*  ei     = d_in[1];
    const void*  batch  = d_in[2];
    const float* Ws     = (const float*)d_in[3];
    const float* bs     = (const float*)d_in[4];
    const float* gammas = (const float*)d_in[5];
    const float* betas  = (const float*)d_in[6];
    const float* lin_w  = (const float*)d_in[7];
    const float* lin_b  = (const float*)d_in[8];

    int n = in_sizes[0] / DD;   // 100000
    int e = in_sizes[1] / 2;    // 1600000

    static int smem_set = 0;
    if (!smem_set) {
        cudaFuncSetAttribute(k_transform_mma,
                             cudaFuncAttributeMaxDynamicSharedMemorySize, TSMEM);
        smem_set = 1;
    }

    k_zero_detect<<<(NMAX + 255) / 256, 256>>>(ei);
    k_count<<<(e + 255) / 256, 256>>>(ei, batch, e, n);
    k_wprep<<<256, 256>>>(Ws);
    k_x2h<<<(n * 32 + 255) / 256, 256>>>(x, n);

    int nb = (n + 511) / 512;
    k_scan1<<<nb, 512>>>(n);
    k_scan23<<<nb, 512>>>(nb, n);
    k_fill<<<(e + 255) / 256, 256>>>(ei, e);

    const int AGG_BLOCKS = 148 * 8;
    const int T_BLOCKS   = 148 * 2;

    float* bufA; cudaGetSymbolAddress((void**)&bufA, g_bufA);
    float* bufB; cudaGetSymbolAddress((void**)&bufB, g_bufB);

    // layer 0: gather fp16(x), self=x fp32, out=A, relu, no residual
    k_agg<<<AGG_BLOCKS, 256>>>(x, n);
    k_transform_mma<<<T_BLOCKS, 256, TSMEM>>>(bs, gammas, betas, lin_w, batch, 0, 0, 1, 1, 0, 1, n);
    // layer 1: self=A, res=A, out=B, relu
    k_agg<<<AGG_BLOCKS, 256>>>(bufA, n);
    k_transform_mma<<<T_BLOCKS, 256, TSMEM>>>(bs, gammas, betas, lin_w, batch, 1, 1, 2, 1, 0, 1, n);
    // layer 2: self=B, res=B, out=A, relu
    k_agg<<<AGG_BLOCKS, 256>>>(bufB, n);
    k_transform_mma<<<T_BLOCKS, 256, TSMEM>>>(bs, gammas, betas, lin_w, batch, 2, 2, 1, 1, 0, 1, n);
    // layer 3: self=A, res=A, NO store, NO relu, pool fused
    k_agg<<<AGG_BLOCKS, 256>>>(bufA, n);
    k_transform_mma<<<T_BLOCKS, 256, TSMEM>>>(bs, gammas, betas, lin_w, batch, 3, 1, 0, 0, 1, 0, n);

    k_final<<<2, 256>>>(lin_b, (float*)d_out);
}

// round 15
// speedup vs baseline: 1.2063x; 1.2063x over previous
#include <cuda_runtime.h>
#include <cuda_fp16.h>

#define NMAX 100000
#define EMAX 1600000
#define DD 128
#define NG 512

// ---------------- device scratch (static, no allocs) ----------------
__device__ int   g_is64;
__device__ int   g_cnt[NMAX];
__device__ float g_dis[NMAX];
__device__ int   g_tmp[NMAX];
__device__ int   g_bsum[256];
__device__ int   g_rowptr[NMAX + 1];
__device__ int   g_cursor[NMAX];
__device__ int2  g_edge[EMAX];
__device__ __align__(256) float g_bufA[(size_t)NMAX * DD];
__device__ __align__(256) float g_bufB[(size_t)NMAX * DD];
__device__ __align__(256) __half g_agg16[(size_t)NMAX * DD];  // fp16 agg output
__device__ __align__(256) __half g_h16[(size_t)NMAX * DD];    // fp16 gather source
__device__ __align__(256) __half g_W16[4 * DD * DD];          // swizzled W^T fp16
__device__ float g_gsum[NG];
__device__ float g_gcnt[NG];

__device__ __forceinline__ int ld_idx(const void* p, long long i) {
    if (g_is64) return (int)((const long long*)p)[i];
    return ((const int*)p)[i];
}

// createpolicy-based evict_last gather load (legal for any width via cache_hint)
__device__ __forceinline__ unsigned long long mk_policy_el() {
    unsigned long long pol;
    asm("createpolicy.fractional.L2::evict_last.b64 %0, 1.0;" : "=l"(pol));
    return pol;
}
__device__ __forceinline__ uint2 ldg_el(const uint2* p, unsigned long long pol) {
    uint2 v;
    asm("ld.global.nc.L2::cache_hint.v2.u32 {%0,%1}, [%2], %3;"
        : "=r"(v.x), "=r"(v.y) : "l"(p), "l"(pol));
    return v;
}

// ---------------- zero + dtype detect ----------------
__global__ void k_zero_detect(const void* ei) {
    int i = blockIdx.x * blockDim.x + threadIdx.x;
    if (i < NMAX) g_cnt[i] = 0;
    if (i < NG) { g_gsum[i] = 0.f; g_gcnt[i] = 0.f; }
    if (i == 0) {
        const unsigned long long* p = (const unsigned long long*)ei;
        int ok = 1;
        for (int j = 0; j < 16; j++)
            if (p[j] >> 32) ok = 0;
        g_is64 = ok;
    }
}

// ---------------- degree count + graph counts ----------------
__global__ void k_count(const void* ei, const void* batch, int e, int n) {
    int i = blockIdx.x * blockDim.x + threadIdx.x;
    if (i < e) {
        int d = ld_idx(ei, (long long)e + i);
        atomicAdd(&g_cnt[d], 1);
    }
    if (i < n) {
        int g = ld_idx(batch, i);
        atomicAdd(&g_gcnt[g], 1.f);
    }
}

// ---------------- x -> fp16 ----------------
__global__ void k_x2h(const float* __restrict__ x, int n) {
    int i = blockIdx.x * blockDim.x + threadIdx.x;
    if (i >= n * 32) return;
    float4 v = __ldcs(&((const float4*)x)[i]);
    __half2 p0 = __floats2half2_rn(v.x, v.y);
    __half2 p1 = __floats2half2_rn(v.z, v.w);
    uint2 u;
    u.x = *(unsigned*)&p0;
    u.y = *(unsigned*)&p1;
    ((uint2*)g_h16)[i] = u;
}

// ---------------- W -> fp16 transposed + swizzled ----------------
__global__ void k_wprep(const float* __restrict__ Ws) {
    int idx = blockIdx.x * blockDim.x + threadIdx.x;   // 65536
    int l = idx >> 14, rem = idx & 16383;
    int c = rem & 127, k = rem >> 7;
    float w = Ws[l * 16384 + k * 128 + c];
    int kg = k >> 3;
    g_W16[l * 16384 + c * 128 + ((((kg ^ (c & 7)) << 3)) | (k & 7))] = __float2half(w);
}

// ---------------- scan phase 1 ----------------
__global__ void k_scan1(int n) {
    __shared__ int s[512];
    int t = threadIdx.x;
    int i = blockIdx.x * 512 + t;
    int v = (i < n) ? g_cnt[i] : 0;
    s[t] = v;
    __syncthreads();
    for (int off = 1; off < 512; off <<= 1) {
        int x = 0;
        if (t >= off) x = s[t - off];
        __syncthreads();
        s[t] += x;
        __syncthreads();
    }
    if (i < n) g_tmp[i] = s[t];
    if (t == 511) g_bsum[blockIdx.x] = s[511];
}

// ---------------- scan phases 2+3 merged ----------------
__global__ void k_scan23(int nb, int n) {
    __shared__ int sb[256];
    int t = threadIdx.x;
    if (t < 256) sb[t] = (t < nb) ? g_bsum[t] : 0;
    __syncthreads();
    for (int off = 1; off < 256; off <<= 1) {
        int x = 0;
        if (t < 256 && t >= off) x = sb[t - off];
        __syncthreads();
        if (t < 256) sb[t] += x;
        __syncthreads();
    }
    int boff = (blockIdx.x > 0) ? sb[blockIdx.x - 1] : 0;
    if (blockIdx.x == 0 && t == 0) g_rowptr[n] = sb[255];
    int i = blockIdx.x * 512 + t;
    if (i < n) {
        int rp = g_tmp[i] - g_cnt[i] + boff;
        g_rowptr[i] = rp;
        g_cursor[i] = rp;
        g_dis[i] = rsqrtf((float)g_cnt[i] + 1.0f);
    }
}

// ---------------- CSR fill ----------------
__global__ void k_fill(const void* ei, int e) {
    int i = blockIdx.x * blockDim.x + threadIdx.x;
    if (i < e) {
        int s = ld_idx(ei, i);
        int d = ld_idx(ei, (long long)e + i);
        int pos = atomicAdd(&g_cursor[d], 1);
        g_edge[pos] = make_int2(s, __float_as_int(g_dis[s] * g_dis[d]));
    }
}

// ---------------- aggregation: warp per node, fp16 gather (evict_last policy), fp16 out ----------------
__global__ __launch_bounds__(256, 8) void k_agg(const float* __restrict__ selfbuf, int n) {
    int nwarps = gridDim.x << 3;
    int lane = threadIdx.x & 31;
    const uint2* in8 = (const uint2*)g_h16;
    unsigned long long pol = mk_policy_el();
    for (int w = (blockIdx.x << 3) + (threadIdx.x >> 5); w < n; w += nwarps) {
        float ds = g_dis[w];
        float self = ds * ds;
        float4 a = __ldcs(&((const float4*)selfbuf)[(size_t)w * 32 + lane]);
        float4 acc;
        acc.x = a.x * self; acc.y = a.y * self; acc.z = a.z * self; acc.w = a.w * self;

        int beg = g_rowptr[w], end = g_rowptr[w + 1];
        for (int base = beg; base < end; base += 32) {
            int e = base + lane;
            int s = 0; float c = 0.f;
            if (e < end) { int2 ed = g_edge[e]; s = ed.x; c = __int_as_float(ed.y); }
            int m = min(32, end - base);
            int k = 0;
            for (; k + 8 <= m; k += 8) {
                int si[8]; float ci[8]; uint2 ui[8];
#pragma unroll
                for (int j = 0; j < 8; j++) {
                    si[j] = __shfl_sync(0xffffffffu, s, k + j);
                    ci[j] = __shfl_sync(0xffffffffu, c, k + j);
                }
#pragma unroll
                for (int j = 0; j < 8; j++) ui[j] = ldg_el(&in8[(size_t)si[j] * 32 + lane], pol);
#pragma unroll
                for (int j = 0; j < 8; j++) {
                    float2 fa = __half22float2(*(__half2*)&ui[j].x);
                    float2 fb = __half22float2(*(__half2*)&ui[j].y);
                    acc.x += ci[j] * fa.x; acc.y += ci[j] * fa.y;
                    acc.z += ci[j] * fb.x; acc.w += ci[j] * fb.y;
                }
            }
            for (; k < m; k++) {
                int ss = __shfl_sync(0xffffffffu, s, k);
                float cc = __shfl_sync(0xffffffffu, c, k);
                uint2 u = ldg_el(&in8[(size_t)ss * 32 + lane], pol);
                float2 fa = __half22float2(*(__half2*)&u.x);
                float2 fb = __half22float2(*(__half2*)&u.y);
                acc.x += cc * fa.x; acc.y += cc * fa.y; acc.z += cc * fb.x; acc.w += cc * fb.y;
            }
        }
        // write fp16 (same rounding point the transform used before — numerics unchanged)
        __half2 h0 = __floats2half2_rn(acc.x, acc.y);
        __half2 h1 = __floats2half2_rn(acc.z, acc.w);
        uint2 u;
        u.x = *(unsigned*)&h0;
        u.y = *(unsigned*)&h1;
        __stcs(&((uint2*)g_agg16)[(size_t)w * 32 + lane], u);
    }
}

// ---------------- tensor-core transform: HMMA GEMM + bias + LN + res + relu + pool ----------------
#define TSMEM (16384 + 32768 + 3 * 512)

__global__ void k_transform_mma(
    const float* __restrict__ bs,
    const float* __restrict__ gammas, const float* __restrict__ betas,
    const float* __restrict__ lin_w, const void* __restrict__ batch,
    int layer, int ressel, int outsel, int dorelu, int dopool, int doh16, int n)
{
    extern __shared__ char smem[];
    __half* sA = (__half*)smem;                       // swizzled: r*128 + ((kg^(r&7))<<3 | k&7)
    __half* sW = (__half*)(smem + 16384);             // swizzled-T: c*128 + ((kg^(c&7))<<3 | k&7)
    float*  sS = (float*)(smem + 49152);              // [2][64]
    float*  sQ = sS + 128;
    float*  sP = sQ + 128;

    int t = threadIdx.x;
    int warp = t >> 5, lane = t & 31;
    int rt = warp >> 1, cgp = warp & 1;
    int g = lane >> 2, tq = lane & 3;

    {
        const uint4* src = (const uint4*)(g_W16 + (size_t)layer * DD * DD);
        uint4* dst = (uint4*)sW;
#pragma unroll
        for (int j = 0; j < 8; j++) dst[t + j * 256] = src[t + j * 256];
    }

    int mi = lane >> 3, li = lane & 7;
    int r_lm = rt * 16 + ((mi & 1) << 3) + li;
    int kgx = mi >> 1;
    unsigned sA_u32 = (unsigned)__cvta_generic_to_shared(sA);
    unsigned aRowBase = sA_u32 + r_lm * 256;

    const float2* res2 = (ressel == 1) ? (const float2*)g_bufA
                       : (ressel == 2) ? (const float2*)g_bufB : (const float2*)0;
    float2* out2 = (outsel == 1) ? (float2*)g_bufA
                 : (outsel == 2) ? (float2*)g_bufB : (float2*)0;

    int ntiles = (n + 63) >> 6;
    for (int tile = blockIdx.x; tile < ntiles; tile += gridDim.x) {
        int row0 = tile << 6;
        __syncthreads();

        // stage A tile: raw fp16 uint4 copy into swizzled smem
        {
            const uint4* agg16 = (const uint4*)g_agg16;   // one row = 16 uint4
#pragma unroll
            for (int j = 0; j < 4; j++) {
                int idx = t + j * 256;
                int r = idx >> 4, kg = idx & 15;
                int row = row0 + r;
                uint4 u = (row < n) ? __ldcs(&agg16[(size_t)row * 16 + kg])
                                    : make_uint4(0u, 0u, 0u, 0u);
                *(uint4*)&sA[r * 128 + ((kg ^ (r & 7)) << 3)] = u;
            }
        }
        __syncthreads();

        float d[8][4];
#pragma unroll
        for (int i = 0; i < 8; i++) { d[i][0] = 0.f; d[i][1] = 0.f; d[i][2] = 0.f; d[i][3] = 0.f; }

#pragma unroll
        for (int ks = 0; ks < 8; ks++) {
            int kg = 2 * ks + kgx;
            unsigned addr = aRowBase + ((kg ^ (r_lm & 7)) << 4);
            unsigned a0, a1, a2, a3;
            asm volatile("ldmatrix.sync.aligned.m8n8.x4.shared.b16 {%0,%1,%2,%3}, [%4];"
                         : "=r"(a0), "=r"(a1), "=r"(a2), "=r"(a3) : "r"(addr));
            int k0 = ks * 16 + 2 * tq;
            int kga = (k0 >> 3), kgb = ((k0 + 8) >> 3);
#pragma unroll
            for (int nt = 0; nt < 8; nt++) {
                int c = cgp * 64 + nt * 8 + g;
                unsigned b0 = *(unsigned*)&sW[c * 128 + (((kga ^ (c & 7)) << 3) | (k0 & 7))];
                unsigned b1 = *(unsigned*)&sW[c * 128 + (((kgb ^ (c & 7)) << 3) | (k0 & 7))];
                asm("mma.sync.aligned.m16n8k16.row.col.f32.f16.f16.f32 "
                    "{%0,%1,%2,%3}, {%4,%5,%6,%7}, {%8,%9}, {%0,%1,%2,%3};"
                    : "+f"(d[nt][0]), "+f"(d[nt][1]), "+f"(d[nt][2]), "+f"(d[nt][3])
                    : "r"(a0), "r"(a1), "r"(a2), "r"(a3), "r"(b0), "r"(b1));
            }
        }

#pragma unroll
        for (int nt = 0; nt < 8; nt++) {
            int cb = cgp * 64 + nt * 8 + 2 * tq;
            float2 bv = *(const float2*)&bs[layer * DD + cb];
            d[nt][0] += bv.x; d[nt][1] += bv.y;
            d[nt][2] += bv.x; d[nt][3] += bv.y;
        }

        float sG = 0.f, qG = 0.f, sH = 0.f, qH = 0.f;
#pragma unroll
        for (int nt = 0; nt < 8; nt++) {
            sG += d[nt][0] + d[nt][1];
            qG += d[nt][0] * d[nt][0] + d[nt][1] * d[nt][1];
            sH += d[nt][2] + d[nt][3];
            qH += d[nt][2] * d[nt][2] + d[nt][3] * d[nt][3];
        }
#pragma unroll
        for (int off = 1; off <= 2; off <<= 1) {
            sG += __shfl_xor_sync(0xffffffffu, sG, off);
            qG += __shfl_xor_sync(0xffffffffu, qG, off);
            sH += __shfl_xor_sync(0xffffffffu, sH, off);
            qH += __shfl_xor_sync(0xffffffffu, qH, off);
        }
        int rA_l = rt * 16 + g, rB_l = rA_l + 8;
        if (tq == 0) {
            sS[cgp * 64 + rA_l] = sG; sQ[cgp * 64 + rA_l] = qG;
            sS[cgp * 64 + rB_l] = sH; sQ[cgp * 64 + rB_l] = qH;
        }
        __syncthreads();
        float sa = sS[rA_l] + sS[64 + rA_l];
        float qa = sQ[rA_l] + sQ[64 + rA_l];
        float sb2 = sS[rB_l] + sS[64 + rB_l];
        float qb2 = sQ[rB_l] + sQ[64 + rB_l];
        float muA = sa * (1.0f / 128.0f);
        float isdA = rsqrtf(qa * (1.0f / 128.0f) - muA * muA + 1e-5f);
        float muB = sb2 * (1.0f / 128.0f);
        float isdB = rsqrtf(qb2 * (1.0f / 128.0f) - muB * muB + 1e-5f);

        int rowA = row0 + rA_l;
        int rowB = row0 + rB_l;
        bool okA = rowA < n, okB = rowB < n;
        float pA = 0.f, pB = 0.f;

#pragma unroll
        for (int nt = 0; nt < 8; nt++) {
            int cb = cgp * 64 + nt * 8 + 2 * tq;
            float2 gv = *(const float2*)&gammas[layer * DD + cb];
            float2 be = *(const float2*)&betas[layer * DD + cb];
            float o0 = (d[nt][0] - muA) * isdA * gv.x + be.x;
            float o1 = (d[nt][1] - muA) * isdA * gv.y + be.y;
            float o2 = (d[nt][2] - muB) * isdB * gv.x + be.x;
            float o3 = (d[nt][3] - muB) * isdB * gv.y + be.y;
            if (res2) {
                if (okA) { float2 r = __ldcs(&res2[(size_t)rowA * 64 + (cb >> 1)]); o0 += r.x; o1 += r.y; }
                if (okB) { float2 r = __ldcs(&res2[(size_t)rowB * 64 + (cb >> 1)]); o2 += r.x; o3 += r.y; }
            }
            if (dorelu) {
                o0 = fmaxf(o0, 0.f); o1 = fmaxf(o1, 0.f);
                o2 = fmaxf(o2, 0.f); o3 = fmaxf(o3, 0.f);
            }
            if (out2) {
                if (okA) __stcs(&out2[(size_t)rowA * 64 + (cb >> 1)], make_float2(o0, o1));
                if (okB) __stcs(&out2[(size_t)rowB * 64 + (cb >> 1)], make_float2(o2, o3));
            }
            if (doh16) {
                if (okA) {
                    __half2 hh = __floats2half2_rn(o0, o1);
                    *(__half2*)&g_h16[(size_t)rowA * DD + cb] = hh;
                }
                if (okB) {
                    __half2 hh = __floats2half2_rn(o2, o3);
                    *(__half2*)&g_h16[(size_t)rowB * DD + cb] = hh;
                }
            }
            if (dopool) {
                float2 lw = *(const float2*)&lin_w[cb];
                pA += o0 * lw.x + o1 * lw.y;
                pB += o2 * lw.x + o3 * lw.y;
            }
        }

        if (dopool) {
#pragma unroll
            for (int off = 1; off <= 2; off <<= 1) {
                pA += __shfl_xor_sync(0xffffffffu, pA, off);
                pB += __shfl_xor_sync(0xffffffffu, pB, off);
            }
            if (tq == 0) {
                sP[cgp * 64 + rA_l] = pA;
                sP[cgp * 64 + rB_l] = pB;
            }
            __syncthreads();
            if (t < 64) {
                int row = row0 + t;
                if (row < n) {
                    float p = sP[t] + sP[64 + t];
                    int gr = ld_idx(batch, row);
                    atomicAdd(&g_gsum[gr], p);
                }
            }
        }
    }
}

// ---------------- final ----------------
__global__ void k_final(const float* __restrict__ lin_b, float* __restrict__ out) {
    int g = blockIdx.x * blockDim.x + threadIdx.x;
    if (g < NG) out[g] = g_gsum[g] / fmaxf(g_gcnt[g], 1.f) + lin_b[0];
}

// ---------------- launch ----------------
extern "C" void kernel_launch(void* const* d_in, const int* in_sizes, int n_in,
                              void* d_out, int out_size) {
    const float* x      = (const float*)d_in[0];
    const void*  ei     = d_in[1];
    const void*  batch  = d_in[2];
    const float* Ws     = (const float*)d_in[3];
    const float* bs     = (const float*)d_in[4];
    const float* gammas = (const float*)d_in[5];
    const float* betas  = (const float*)d_in[6];
    const float* lin_w  = (const float*)d_in[7];
    const float* lin_b  = (const float*)d_in[8];

    int n = in_sizes[0] / DD;   // 100000
    int e = in_sizes[1] / 2;    // 1600000

    static int smem_set = 0;
    if (!smem_set) {
        cudaFuncSetAttribute(k_transform_mma,
                             cudaFuncAttributeMaxDynamicSharedMemorySize, TSMEM);
        smem_set = 1;
    }

    k_zero_detect<<<(NMAX + 255) / 256, 256>>>(ei);
    k_count<<<(e + 255) / 256, 256>>>(ei, batch, e, n);
    k_wprep<<<256, 256>>>(Ws);
    k_x2h<<<(n * 32 + 255) / 256, 256>>>(x, n);

    int nb = (n + 511) / 512;
    k_scan1<<<nb, 512>>>(n);
    k_scan23<<<nb, 512>>>(nb, n);
    k_fill<<<(e + 255) / 256, 256>>>(ei, e);

    const int AGG_BLOCKS = 148 * 8;
    const int T_BLOCKS   = 148 * 2;

    float* bufA; cudaGetSymbolAddress((void**)&bufA, g_bufA);
    float* bufB; cudaGetSymbolAddress((void**)&bufB, g_bufB);

    // layer 0: gather fp16(x), self=x fp32, out=A, relu, no residual
    k_agg<<<AGG_BLOCKS, 256>>>(x, n);
    k_transform_mma<<<T_BLOCKS, 256, TSMEM>>>(bs, gammas, betas, lin_w, batch, 0, 0, 1, 1, 0, 1, n);
    // layer 1: self=A, res=A, out=B, relu
    k_agg<<<AGG_BLOCKS, 256>>>(bufA, n);
    k_transform_mma<<<T_BLOCKS, 256, TSMEM>>>(bs, gammas, betas, lin_w, batch, 1, 1, 2, 1, 0, 1, n);
    // layer 2: self=B, res=B, out=A, relu
    k_agg<<<AGG_BLOCKS, 256>>>(bufB, n);
    k_transform_mma<<<T_BLOCKS, 256, TSMEM>>>(bs, gammas, betas, lin_w, batch, 2, 2, 1, 1, 0, 1, n);
    // layer 3: self=A, res=A, NO store, NO relu, pool fused
    k_agg<<<AGG_BLOCKS, 256>>>(bufA, n);
    k_transform_mma<<<T_BLOCKS, 256, TSMEM>>>(bs, gammas, betas, lin_w, batch, 3, 1, 0, 0, 1, 0, n);

    k_final<<<2, 256>>>(lin_b, (float*)d_out);
}